// round 15
// baseline (speedup 1.0000x reference)
#include <cuda_runtime.h>
#include <cuda_bf16.h>
#include <math.h>
#include <stdint.h>

#if defined(__CUDA_ARCH__) && (defined(__CUDA_ARCH_FEAT_SM103_ALL) || (defined(__CUDA_ARCH_SPECIFIC__) && (__CUDA_ARCH_SPECIFIC__ == 1030)))
#define T5_OK 1
#else
#define T5_OK 0
#endif

#define BB 2
#define SS 2048
#define DIM 2048
#define HH 16
#define KVR 512
#define NOPE 128
#define ROPE 64
#define VDIM 128
#define QK 192
#define BS (BB*SS)
#define SCALE_C 0.07216878364870322f

__device__ float g_KV [(size_t)BS * (KVR+ROPE)];
__device__ float g_V  [(size_t)BS * (HH*VDIM)];

#define APAN 8192
#define BPAN 16384
__device__ __align__(1024) __nv_bfloat16 g_Xh [(size_t)32*32*APAN],  g_Xl [(size_t)32*32*APAN];
__device__ __align__(1024) __nv_bfloat16 g_WQh[(size_t)12*32*BPAN],  g_WQl[(size_t)12*32*BPAN];
__device__ __align__(1024) __nv_bfloat16 g_WAh[(size_t)3*32*BPAN],   g_WAl[(size_t)3*32*BPAN];
__device__ __align__(1024) __nv_bfloat16 g_WBkh[(size_t)8*8*BPAN],   g_WBkl[(size_t)8*8*BPAN];
__device__ __align__(1024) __nv_bfloat16 g_WBvh[(size_t)8*8*BPAN],   g_WBvl[(size_t)8*8*BPAN];
__device__ __align__(1024) __nv_bfloat16 g_WOh[(size_t)8*32*BPAN],   g_WOl[(size_t)8*32*BPAN];
__device__ __align__(1024) __nv_bfloat16 g_CKVh[(size_t)32*8*APAN],  g_CKVl[(size_t)32*8*APAN];
__device__ __align__(1024) __nv_bfloat16 g_OHh[(size_t)32*32*APAN],  g_OHl[(size_t)32*32*APAN];
__device__ __align__(1024) __nv_bfloat16 g_Qp [(size_t)512*49152];
__device__ __align__(1024) __nv_bfloat16 g_Kp [(size_t)1024*24576];
__device__ __align__(1024) __nv_bfloat16 g_Vp [(size_t)1024*16384];

__device__ __forceinline__ uint32_t swz(uint32_t off) { return off ^ ((off >> 3) & 0x70); }

#if T5_OK
__device__ __forceinline__ uint32_t smem_u32(const void* p) {
    uint32_t a;
    asm("{ .reg .u64 t; cvta.to.shared.u64 t, %1; cvt.u32.u64 %0, t; }" : "=r"(a) : "l"(p));
    return a;
}
__device__ __forceinline__ uint32_t elect_one() {
    uint32_t p;
    asm volatile("{\n\t.reg .pred p;\n\telect.sync _|p, 0xFFFFFFFF;\n\tselp.b32 %0, 1, 0, p;\n\t}" : "=r"(p));
    return p;
}
__device__ __forceinline__ void mbar_init(uint32_t a, uint32_t n) {
    asm volatile("mbarrier.init.shared.b64 [%0], %1;" :: "r"(a), "r"(n) : "memory");
}
__device__ __forceinline__ void mbar_inval(uint32_t a) {
    asm volatile("mbarrier.inval.shared.b64 [%0];" :: "r"(a) : "memory");
}
__device__ __forceinline__ void mbar_arrive(uint32_t a) {
    asm volatile("mbarrier.arrive.shared.b64 _, [%0];" :: "r"(a) : "memory");
}
__device__ __forceinline__ void mbar_expect_tx(uint32_t a, uint32_t bytes) {
    asm volatile("mbarrier.arrive.expect_tx.shared.b64 _, [%0], %1;" :: "r"(a), "r"(bytes) : "memory");
}
__device__ __forceinline__ void mbar_wait(uint32_t a, uint32_t parity) {
    asm volatile(
        "{\n\t.reg .pred P;\n\t"
        "W_%=:\n\t"
        "mbarrier.try_wait.parity.acquire.cta.shared::cta.b64 P, [%0], %1, 0x989680;\n\t"
        "@P bra.uni D_%=;\n\t"
        "bra.uni W_%=;\n\t"
        "D_%=:\n\t}"
        :: "r"(a), "r"(parity) : "memory");
}
__device__ __forceinline__ void bulk_g2s(uint32_t dst, const void* src, uint32_t bytes, uint32_t mbar) {
    asm volatile(
        "cp.async.bulk.shared::cta.global.mbarrier::complete_tx::bytes [%0], [%1], %2, [%3];"
        :: "r"(dst), "l"(src), "r"(bytes), "r"(mbar) : "memory");
}
__device__ __forceinline__ void t5_alloc(uint32_t smem_res, uint32_t ncols) {
    asm volatile("tcgen05.alloc.cta_group::1.sync.aligned.shared::cta.b32 [%0], %1;"
                 :: "r"(smem_res), "r"(ncols) : "memory");
}
__device__ __forceinline__ void t5_dealloc(uint32_t tmem, uint32_t ncols) {
    asm volatile("tcgen05.dealloc.cta_group::1.sync.aligned.b32 %0, %1;" :: "r"(tmem), "r"(ncols));
}
__device__ __forceinline__ void t5_commit(uint32_t mbar) {
    asm volatile("tcgen05.commit.cta_group::1.mbarrier::arrive::one.shared::cluster.b64 [%0];"
                 :: "r"(mbar) : "memory");
}
__device__ __forceinline__ void t5_fence_after()  { asm volatile("tcgen05.fence::after_thread_sync;" ::: "memory"); }
__device__ __forceinline__ void t5_fence_before() { asm volatile("tcgen05.fence::before_thread_sync;" ::: "memory"); }
__device__ __forceinline__ void t5_wait_ld()      { asm volatile("tcgen05.wait::ld.sync.aligned;" ::: "memory"); }
__device__ __forceinline__ void t5_wait_st()      { asm volatile("tcgen05.wait::st.sync.aligned;" ::: "memory"); }
__device__ __forceinline__ void fence_pa()        { asm volatile("fence.proxy.async.shared::cta;" ::: "memory"); }
__device__ __forceinline__ void t5_mma_f16_ss(uint32_t d, uint64_t ad, uint64_t bd,
                                              uint32_t idesc, uint32_t en) {
    asm volatile(
        "{\n\t.reg .pred p;\n\t"
        "setp.ne.u32 p, %4, 0;\n\t"
        "tcgen05.mma.cta_group::1.kind::f16 [%0], %1, %2, %3, {%5,%5,%5,%5}, p;\n\t}"
        :: "r"(d), "l"(ad), "l"(bd), "r"(idesc), "r"(en), "r"(0u) : "memory");
}
__device__ __forceinline__ void t5_mma_f16_ts(uint32_t d, uint32_t at, uint64_t bd,
                                              uint32_t idesc, uint32_t en) {
    asm volatile(
        "{\n\t.reg .pred p;\n\t"
        "setp.ne.u32 p, %4, 0;\n\t"
        "tcgen05.mma.cta_group::1.kind::f16 [%0], [%1], %2, %3, {%5,%5,%5,%5}, p;\n\t}"
        :: "r"(d), "r"(at), "l"(bd), "r"(idesc), "r"(en), "r"(0u) : "memory");
}
__device__ __forceinline__ void ldtm_x32(uint32_t* d, uint32_t addr) {
    asm volatile(
        "tcgen05.ld.sync.aligned.32x32b.x32.b32 "
        "{%0, %1, %2, %3, %4, %5, %6, %7, "
        " %8, %9, %10, %11, %12, %13, %14, %15, "
        " %16, %17, %18, %19, %20, %21, %22, %23, "
        " %24, %25, %26, %27, %28, %29, %30, %31}, [%32];"
        : "=r"(d[0]),  "=r"(d[1]),  "=r"(d[2]),  "=r"(d[3]),
          "=r"(d[4]),  "=r"(d[5]),  "=r"(d[6]),  "=r"(d[7]),
          "=r"(d[8]),  "=r"(d[9]),  "=r"(d[10]), "=r"(d[11]),
          "=r"(d[12]), "=r"(d[13]), "=r"(d[14]), "=r"(d[15]),
          "=r"(d[16]), "=r"(d[17]), "=r"(d[18]), "=r"(d[19]),
          "=r"(d[20]), "=r"(d[21]), "=r"(d[22]), "=r"(d[23]),
          "=r"(d[24]), "=r"(d[25]), "=r"(d[26]), "=r"(d[27]),
          "=r"(d[28]), "=r"(d[29]), "=r"(d[30]), "=r"(d[31])
        : "r"(addr));
}
__device__ __forceinline__ void sttm_x32(uint32_t addr, const uint32_t* r) {
    asm volatile(
        "tcgen05.st.sync.aligned.32x32b.x32.b32 [%0], "
        "{%1, %2, %3, %4, %5, %6, %7, %8, "
        " %9, %10, %11, %12, %13, %14, %15, %16, "
        " %17, %18, %19, %20, %21, %22, %23, %24, "
        " %25, %26, %27, %28, %29, %30, %31, %32};"
        :: "r"(addr),
           "r"(r[0]),  "r"(r[1]),  "r"(r[2]),  "r"(r[3]),
           "r"(r[4]),  "r"(r[5]),  "r"(r[6]),  "r"(r[7]),
           "r"(r[8]),  "r"(r[9]),  "r"(r[10]), "r"(r[11]),
           "r"(r[12]), "r"(r[13]), "r"(r[14]), "r"(r[15]),
           "r"(r[16]), "r"(r[17]), "r"(r[18]), "r"(r[19]),
           "r"(r[20]), "r"(r[21]), "r"(r[22]), "r"(r[23]),
           "r"(r[24]), "r"(r[25]), "r"(r[26]), "r"(r[27]),
           "r"(r[28]), "r"(r[29]), "r"(r[30]), "r"(r[31])
        : "memory");
}
static __device__ __forceinline__ uint64_t mk_desc(uint32_t addr) {
    const uint64_t base = (uint64_t(2) << 61) | (uint64_t(1) << 46)
                        | (uint64_t(64) << 32) | (uint64_t(1) << 16);
    return base | ((uint64_t)(addr >> 4) & 0x3FFF);
}
#define T5_IDESC ((1u<<4)|(1u<<7)|(1u<<10)|(32u<<17)|(8u<<24))
#define IDESC_QK ((1u<<4)|(1u<<7)|(1u<<10)|(8u<<17)|(8u<<24))
#define IDESC_PV ((1u<<4)|(1u<<7)|(1u<<10)|(16u<<17)|(8u<<24))
#endif

// ---------------- split kernels ----------------
__global__ void split_A_kernel(const float* __restrict__ src,
                               __nv_bfloat16* __restrict__ dh, __nv_bfloat16* __restrict__ dl,
                               int K, int nchunks)
{
#if T5_OK
    size_t i = (size_t)blockIdx.x * 256 + threadIdx.x;
    if (i >= (size_t)BS * K) return;
    int row = (int)(i / K), k = (int)(i % K);
    float v = src[i];
    int tile = row >> 7, rin = row & 127, chunk = k >> 6, cin = k & 63;
    uint32_t sw = swz((uint32_t)(rin * 128 + cin * 2));
    size_t idx = ((size_t)(tile * nchunks + chunk) << 13) + (sw >> 1);
    __nv_bfloat16 h = __float2bfloat16(v);
    dh[idx] = h;
    dl[idx] = __float2bfloat16(v - __bfloat162float(h));
#endif
}

__global__ void split_B_kernel(const float* __restrict__ src,
                               __nv_bfloat16* __restrict__ dh, __nv_bfloat16* __restrict__ dl,
                               int Nrows, int K, int group, int gstride, int gbase, size_t total)
{
#if T5_OK
    size_t i = (size_t)blockIdx.x * 256 + threadIdx.x;
    if (i >= total) return;
    int n = (int)(i / K), k = (int)(i % K);
    float v = 0.f;
    if (n < Nrows) {
        int br = gbase + (n / group) * gstride + (n % group);
        v = src[(size_t)br * K + k];
    }
    int tile = n >> 8, rin = n & 255, chunk = k >> 6, cin = k & 63;
    int nchunks = K >> 6;
    uint32_t sw = swz((uint32_t)(rin * 128 + cin * 2));
    size_t idx = ((size_t)(tile * nchunks + chunk) << 14) + (sw >> 1);
    __nv_bfloat16 h = __float2bfloat16(v);
    dh[idx] = h;
    dl[idx] = __float2bfloat16(v - __bfloat162float(h));
#endif
}

// ---------------- tcgen05 bf16x3 GEMM (R11-proven core + epilogue modes) ----------------
#define SM_TMPTR 0
#define SM_FULL0 16
#define SM_FREE0 32
#define SM_DONE  48
#define SM_STG0  1024
#define STG_BYTES 98304
#define OFF_AH 0
#define OFF_AL 16384
#define OFF_BH 32768
#define OFF_BL 65536
#define GEMM_SMEM (1024 + 2*STG_BYTES)

__global__ __launch_bounds__(128, 1)
void gemm_t5(const __nv_bfloat16* __restrict__ Ah, const __nv_bfloat16* __restrict__ Al,
             const __nv_bfloat16* __restrict__ Bh, const __nv_bfloat16* __restrict__ Bl,
             float* __restrict__ C, __nv_bfloat16* __restrict__ pan,
             int N, int nchunks, int mode,
             const float* __restrict__ COS, const float* __restrict__ SIN)
{
#if T5_OK
    extern __shared__ __align__(1024) char smraw[];
    const uint32_t smb = smem_u32(smraw);
    const int tid  = threadIdx.x;
    const int warp = tid >> 5;
    const int lane = tid & 31;
    const int tile_n = blockIdx.x;
    const int tile_m = blockIdx.y;

    if (tid == 0) {
        mbar_init(smb + SM_FULL0 + 0, 1);
        mbar_init(smb + SM_FULL0 + 8, 1);
        mbar_init(smb + SM_FREE0 + 0, 1);
        mbar_init(smb + SM_FREE0 + 8, 1);
        mbar_init(smb + SM_DONE, 1);
    }
    if (warp == 1) t5_alloc(smb + SM_TMPTR, 512);
    __syncthreads();
    uint32_t tmem;
    asm volatile("ld.shared.b32 %0, [%1];" : "=r"(tmem) : "r"(smb + SM_TMPTR));

    if (warp == 0) {
        if (elect_one()) {
            uint32_t pph = 1;
            const size_t abase = (size_t)tile_m * nchunks;
            const size_t bbase = (size_t)tile_n * nchunks;
            for (int c = 0; c < nchunks; c++) {
                int s = c & 1;
                uint32_t stg = smb + SM_STG0 + s * STG_BYTES;
                mbar_wait(smb + SM_FREE0 + s * 8, pph);
                mbar_expect_tx(smb + SM_FULL0 + s * 8, STG_BYTES);
                bulk_g2s(stg + OFF_AH, Ah + (abase + c) * APAN, 16384, smb + SM_FULL0 + s * 8);
                bulk_g2s(stg + OFF_AL, Al + (abase + c) * APAN, 16384, smb + SM_FULL0 + s * 8);
                bulk_g2s(stg + OFF_BH, Bh + (bbase + c) * BPAN, 32768, smb + SM_FULL0 + s * 8);
                bulk_g2s(stg + OFF_BL, Bl + (bbase + c) * BPAN, 32768, smb + SM_FULL0 + s * 8);
                if (s == 1) pph ^= 1;
            }
        }
    }
    if (warp == 1) {
        if (elect_one()) {
            uint32_t cph = 0;
            for (int c = 0; c < nchunks; c++) {
                int s = c & 1;
                uint32_t stg = smb + SM_STG0 + s * STG_BYTES;
                mbar_wait(smb + SM_FULL0 + s * 8, cph);
                uint64_t ahd = mk_desc(stg + OFF_AH);
                uint64_t ald = mk_desc(stg + OFF_AL);
                uint64_t bhd = mk_desc(stg + OFF_BH);
                uint64_t bld = mk_desc(stg + OFF_BL);
                uint64_t ads[3] = {ahd, ahd, ald};
                uint64_t bds[3] = {bhd, bld, bhd};
                #pragma unroll
                for (int p = 0; p < 3; p++) {
                    #pragma unroll
                    for (int k = 0; k < 4; k++) {
                        uint32_t en = (c | p | k) ? 1u : 0u;
                        t5_mma_f16_ss(tmem, ads[p] + k * 2, bds[p] + k * 2, T5_IDESC, en);
                    }
                }
                t5_commit(smb + SM_FREE0 + s * 8);
                if (c == nchunks - 1) t5_commit(smb + SM_DONE);
                if (s == 1) cph ^= 1;
            }
        }
    }

    mbar_wait(smb + SM_DONE, 0);
    t5_fence_after();

    const int gr = (tile_m << 7) + (warp << 5) + lane;
    #pragma unroll 1
    for (int cb = 0; cb < 8; cb++) {
        uint32_t d[32];
        ldtm_x32(d, tmem + cb * 32);
        t5_wait_ld();
        int gc0 = (tile_n << 8) + (cb << 5);
        if (mode == 0) {
            float* cp = C + (size_t)gr * N + gc0;
            #pragma unroll
            for (int j = 0; j < 32; j += 4) {
                if (gc0 + j < N)
                    *(float4*)(cp + j) = make_float4(__uint_as_float(d[j]),   __uint_as_float(d[j+1]),
                                                     __uint_as_float(d[j+2]), __uint_as_float(d[j+3]));
            }
        } else if (mode == 1) {
            int hh = gc0 / 192;
            int dd0 = gc0 % 192;
            int ch = dd0 >> 6;
            int cin0 = dd0 & 63;
            float vals[32];
            #pragma unroll
            for (int j = 0; j < 32; j++) vals[j] = __uint_as_float(d[j]);
            if (dd0 >= 128) {
                int spos = gr & (SS - 1);
                int i0 = (dd0 - 128) >> 1;
                #pragma unroll
                for (int jp = 0; jp < 16; jp++) {
                    float c  = COS[spos * 32 + i0 + jp];
                    float sn = SIN[spos * 32 + i0 + jp];
                    float xe = vals[2*jp], xo = vals[2*jp + 1];
                    vals[2*jp]     = xe * c - xo * sn;
                    vals[2*jp + 1] = xe * sn + xo * c;
                }
            }
            int bh = (gr >> 11) * 16 + hh;
            int qt = (gr >> 7) & 15;
            int rin = gr & 127;
            size_t pb = (size_t)(bh * 16 + qt) * 49152;
            #pragma unroll
            for (int j = 0; j < 32; j += 2) {
                uint32_t sw = swz((uint32_t)(rin * 128 + (cin0 + j) * 2));
                float v0 = vals[j], v1 = vals[j+1];
                __nv_bfloat16 h0 = __float2bfloat16(v0), h1 = __float2bfloat16(v1);
                __nv_bfloat16 l0 = __float2bfloat16(v0 - __bfloat162float(h0));
                __nv_bfloat16 l1 = __float2bfloat16(v1 - __bfloat162float(h1));
                *(__nv_bfloat162*)&pan[pb + ch * 8192 + (sw >> 1)]         = __halves2bfloat162(h0, h1);
                *(__nv_bfloat162*)&pan[pb + 24576 + ch * 8192 + (sw >> 1)] = __halves2bfloat162(l0, l1);
            }
        } else {
            int hh = gc0 >> 7;
            int dd0 = gc0 & 127;
            int ch = dd0 >> 6;
            int cin0 = dd0 & 63;
            int b = gr >> 11, t = gr & (SS - 1);
            int kt = t >> 6, rin = t & 63;
            size_t pb = (size_t)((b * 16 + hh) * 32 + kt) * 24576;
            #pragma unroll
            for (int j = 0; j < 32; j += 2) {
                uint32_t sw = swz((uint32_t)(rin * 128 + (cin0 + j) * 2));
                float v0 = __uint_as_float(d[j]), v1 = __uint_as_float(d[j+1]);
                __nv_bfloat16 h0 = __float2bfloat16(v0), h1 = __float2bfloat16(v1);
                __nv_bfloat16 l0 = __float2bfloat16(v0 - __bfloat162float(h0));
                __nv_bfloat16 l1 = __float2bfloat16(v1 - __bfloat162float(h1));
                *(__nv_bfloat162*)&pan[pb + ch * 4096 + (sw >> 1)]         = __halves2bfloat162(h0, h1);
                *(__nv_bfloat162*)&pan[pb + 12288 + ch * 4096 + (sw >> 1)] = __halves2bfloat162(l0, l1);
            }
        }
    }

    __syncthreads();
    if (tid == 0) {
        mbar_inval(smb + SM_FULL0 + 0); mbar_inval(smb + SM_FULL0 + 8);
        mbar_inval(smb + SM_FREE0 + 0); mbar_inval(smb + SM_FREE0 + 8);
        mbar_inval(smb + SM_DONE);
    }
    if (warp == 1) t5_dealloc(tmem, 512);
#endif
}

// ---------------- KV post: rmsnorm -> CKV panels, rope(k_pe) -> Kp chunk 2 ----------------
__global__ void kv_post_kernel(const float* __restrict__ KV,
                               const float* __restrict__ W,
                               const float* __restrict__ COS,
                               const float* __restrict__ SIN,
                               __nv_bfloat16* __restrict__ CKVh,
                               __nv_bfloat16* __restrict__ CKVl,
                               __nv_bfloat16* __restrict__ Kp)
{
#if T5_OK
    __shared__ float red[4];
    __shared__ float rs_s;
    const int m = blockIdx.x;
    const int tid = threadIdx.x;
    const float* row = KV + (size_t)m * (KVR+ROPE);

    float ss = 0.f;
    for (int c = tid; c < KVR; c += 128) { float v = row[c]; ss += v * v; }
    #pragma unroll
    for (int o = 16; o; o >>= 1) ss += __shfl_xor_sync(0xffffffffu, ss, o);
    if ((tid & 31) == 0) red[tid >> 5] = ss;
    __syncthreads();
    if (tid == 0) {
        float t = red[0] + red[1] + red[2] + red[3];
        rs_s = rsqrtf(t / (float)KVR + 1e-6f);
    }
    __syncthreads();
    float rs = rs_s;
    const int tile = m >> 7, rin = m & 127;
    for (int c = tid; c < KVR; c += 128) {
        float v = row[c] * rs * W[c];
        int chunk = c >> 6, cin = c & 63;
        uint32_t sw = swz((uint32_t)(rin * 128 + cin * 2));
        size_t idx = ((size_t)(tile * 8 + chunk) << 13) + (sw >> 1);
        __nv_bfloat16 h = __float2bfloat16(v);
        CKVh[idx] = h;
        CKVl[idx] = __float2bfloat16(v - __bfloat162float(h));
    }
    if (tid < 32) {
        int i = tid;
        int s = m & (SS - 1);
        float xe = row[KVR + 2*i], xo = row[KVR + 2*i + 1];
        float c  = COS[s*32 + i], sn = SIN[s*32 + i];
        float ye = xe*c - xo*sn;
        float yo = xe*sn + xo*c;
        __nv_bfloat16 h0 = __float2bfloat16(ye), h1 = __float2bfloat16(yo);
        __nv_bfloat16 l0 = __float2bfloat16(ye - __bfloat162float(h0));
        __nv_bfloat16 l1 = __float2bfloat16(yo - __bfloat162float(h1));
        __nv_bfloat162 ph = __halves2bfloat162(h0, h1);
        __nv_bfloat162 pl = __halves2bfloat162(l0, l1);
        int b = m >> 11, t = m & (SS - 1);
        int kt = t >> 6, krin = t & 63;
        uint32_t sw = swz((uint32_t)(krin * 128 + (2*i) * 2));
        #pragma unroll 1
        for (int h = 0; h < HH; h++) {
            size_t pb = (size_t)((b * 16 + h) * 32 + kt) * 24576;
            *(__nv_bfloat162*)&Kp[pb + 2*4096 + (sw >> 1)]         = ph;
            *(__nv_bfloat162*)&Kp[pb + 12288 + 2*4096 + (sw >> 1)] = pl;
        }
    }
#endif
}

// ---------------- V panel builder (transpose) ----------------
__global__ __launch_bounds__(256)
void vpanel_kernel(const float* __restrict__ V, __nv_bfloat16* __restrict__ Vp)
{
#if T5_OK
    __shared__ float sm[64][129];
    int blk = blockIdx.x;
    int bh = blk >> 5, kt = blk & 31;
    int b = bh >> 4, h = bh & 15;
    for (int i = threadIdx.x; i < 8192; i += 256) {
        int tt = i >> 7, d = i & 127;
        sm[tt][d] = V[(size_t)(b*SS + kt*64 + tt)*2048 + h*128 + d];
    }
    __syncthreads();
    size_t base = (size_t)blk * 16384;
    for (int i = threadIdx.x; i < 4096; i += 256) {
        int d = i >> 5, tp = (i & 31)*2;
        float v0 = sm[tp][d], v1 = sm[tp+1][d];
        uint32_t sw = swz((uint32_t)(d*128 + tp*2));
        __nv_bfloat16 h0 = __float2bfloat16(v0), h1 = __float2bfloat16(v1);
        __nv_bfloat16 l0 = __float2bfloat16(v0 - __bfloat162float(h0));
        __nv_bfloat16 l1 = __float2bfloat16(v1 - __bfloat162float(h1));
        *(__nv_bfloat162*)&Vp[base + (sw >> 1)]        = __halves2bfloat162(h0, h1);
        *(__nv_bfloat162*)&Vp[base + 8192 + (sw >> 1)] = __halves2bfloat162(l0, l1);
    }
#endif
}

// ---------------- tcgen05 flash attention (pipelined issuer: QK one tile ahead) ----------------
#define MB_KVF 0
#define MB_KVE 16
#define MB_SD  32
#define MB_PR  48
#define MB_PF  56
#define MB_OR  64
#define MB_QL  72
#define SM_TM  80
#define SM_LI  128
#define A2_K0  1024
#define A2_K1  50176
#define A2_V0  99328
#define A2_V1  132096
#define A2_P   164864
#define A2_SMEM 197632

__global__ __launch_bounds__(256, 1)
void attn_t5(const __nv_bfloat16* __restrict__ Qp, const __nv_bfloat16* __restrict__ Kp,
             const __nv_bfloat16* __restrict__ Vp,
             __nv_bfloat16* __restrict__ OHh, __nv_bfloat16* __restrict__ OHl)
{
#if T5_OK
    extern __shared__ __align__(1024) char smraw[];
    const uint32_t smb = smem_u32(smraw);
    float* sLi = (float*)(smraw + SM_LI);
    const int tid = threadIdx.x, warp = tid >> 5, lane = tid & 31;
    const int qt = 15 - blockIdx.x, h = blockIdx.y, b = blockIdx.z;
    const int bh = b*16 + h;
    const int nt = 2*qt + 2;

    if (tid == 0) {
        mbar_init(smb + MB_KVF + 0, 1); mbar_init(smb + MB_KVF + 8, 1);
        mbar_init(smb + MB_KVE + 0, 1); mbar_init(smb + MB_KVE + 8, 1);
        mbar_init(smb + MB_SD  + 0, 1); mbar_init(smb + MB_SD  + 8, 1);
        mbar_init(smb + MB_PR, 4);
        mbar_init(smb + MB_PF, 1);
        mbar_init(smb + MB_OR, 1);
        mbar_init(smb + MB_QL, 1);
    }
    if (warp == 0) t5_alloc(smb + SM_TM, 512);
    __syncthreads();
    uint32_t tmem;
    asm volatile("ld.shared.b32 %0, [%1];" : "=r"(tmem) : "r"(smb + SM_TM));
    uint32_t amI = (warp == 0) ? elect_one() : 0;
    uint32_t amP = (warp == 4) ? elect_one() : 0;

    // Q panel -> smem (bulk) -> TMEM
    if (amI) {
        mbar_expect_tx(smb + MB_QL, 98304);
        bulk_g2s(smb + A2_K0, Qp + (size_t)(bh*16 + qt) * 49152, 98304, smb + MB_QL);
    }
    mbar_wait(smb + MB_QL, 0);
    if (warp < 4) {
        int row = (warp << 5) | lane;
        uint32_t woff = (uint32_t)warp << 21;
        #pragma unroll 1
        for (int c3 = 0; c3 < 3; c3++) {
            uint32_t hi[32], lo[32];
            #pragma unroll
            for (int j = 0; j < 32; j++) {
                uint32_t sw = swz((uint32_t)(row*128 + j*4));
                hi[j] = *(uint32_t*)(smraw + A2_K0 + c3*16384 + sw);
                lo[j] = *(uint32_t*)(smraw + A2_K0 + 49152 + c3*16384 + sw);
            }
            sttm_x32(tmem + 256 + c3*32 + woff, hi);
            sttm_x32(tmem + 352 + c3*32 + woff, lo);
        }
        t5_wait_st();
    }
    t5_fence_before();
    __syncthreads();

    if (amP) {
        for (int t = 0; t < nt; t++) {
            int s = t & 1;
            if (t >= 2) mbar_wait(smb + MB_KVE + s*8, ((t - 2) >> 1) & 1);
            mbar_expect_tx(smb + MB_KVF + s*8, 81920);
            bulk_g2s(smb + (s ? A2_K1 : A2_K0), Kp + (size_t)(bh*32 + t)*24576, 49152, smb + MB_KVF + s*8);
            bulk_g2s(smb + (s ? A2_V1 : A2_V0), Vp + (size_t)(bh*32 + t)*16384, 32768, smb + MB_KVF + s*8);
        }
    }

    if (warp < 4) {
        const int row = (warp << 5) | lane;
        const int grow = qt*128 + row;
        float l = 0.f;
        uint32_t pfp = 0;
        // prologue: issue QK(0)
        if (amI) {
            mbar_wait(smb + MB_KVF + 0, 0);
            bool first = true;
            #pragma unroll
            for (int p = 0; p < 3; p++) {
                uint32_t ab = (p == 2) ? 352u : 256u;
                uint32_t bo = (p == 1) ? 24576u : 0u;
                #pragma unroll
                for (int ks = 0; ks < 12; ks++) {
                    uint64_t kd = mk_desc(smb + A2_K0 + bo + (ks >> 2)*8192) + (ks & 3)*2;
                    t5_mma_f16_ts(tmem, tmem + ab + ks*8, kd, IDESC_QK, first ? 0u : 1u);
                    first = false;
                }
            }
            t5_commit(smb + MB_SD + 0);
        }
        for (int t = 0; t < nt; t++) {
            const int s = t & 1;
            const uint32_t Sb = tmem + s*64;
            // issue QK(t+1) ahead (write-after-read on S slot guaranteed by PR-wait(t-1))
            if (amI && t + 1 < nt) {
                const int s2 = (t + 1) & 1;
                mbar_wait(smb + MB_KVF + s2*8, ((t + 1) >> 1) & 1);
                const uint32_t Kst2 = smb + (s2 ? A2_K1 : A2_K0);
                bool first = true;
                #pragma unroll
                for (int p = 0; p < 3; p++) {
                    uint32_t ab = (p == 2) ? 352u : 256u;
                    uint32_t bo = (p == 1) ? 24576u : 0u;
                    #pragma unroll
                    for (int ks = 0; ks < 12; ks++) {
                        uint64_t kd = mk_desc(Kst2 + bo + (ks >> 2)*8192) + (ks & 3)*2;
                        t5_mma_f16_ts(tmem + s2*64, tmem + ab + ks*8, kd, IDESC_QK, first ? 0u : 1u);
                        first = false;
                    }
                }
                t5_commit(smb + MB_SD + s2*8);
            }
            mbar_wait(smb + MB_SD + s*8, (t >> 1) & 1);
            t5_fence_after();
            float sv[64];
            ldtm_x32((uint32_t*)sv, Sb);
            ldtm_x32((uint32_t*)(sv + 32), Sb + 32);
            t5_wait_ld(); t5_fence_before();
            const int t0 = t*64;
            #pragma unroll
            for (int j = 0; j < 64; j++) {
                float e = (t0 + j > grow) ? 0.f : __expf(sv[j] * SCALE_C);
                sv[j] = e;
                l += e;
            }
            if (t > 0) { mbar_wait(smb + MB_PF, pfp); pfp ^= 1; }
            #pragma unroll
            for (int j = 0; j < 64; j += 2) {
                uint32_t sw = swz((uint32_t)(row*128 + j*2));
                __nv_bfloat16 h0 = __float2bfloat16(sv[j]), h1 = __float2bfloat16(sv[j+1]);
                __nv_bfloat16 l0 = __float2bfloat16(sv[j]   - __bfloat162float(h0));
                __nv_bfloat16 l1 = __float2bfloat16(sv[j+1] - __bfloat162float(h1));
                *(__nv_bfloat162*)(smraw + A2_P + sw)         = __halves2bfloat162(h0, h1);
                *(__nv_bfloat162*)(smraw + A2_P + 16384 + sw) = __halves2bfloat162(l0, l1);
            }
            fence_pa();
            if (elect_one()) mbar_arrive(smb + MB_PR);
            if (amI) {
                mbar_wait(smb + MB_PR, t & 1);
                const uint32_t Vst = smb + (s ? A2_V1 : A2_V0);
                bool first = true;
                #pragma unroll
                for (int p = 0; p < 3; p++) {
                    uint64_t pd = mk_desc(smb + A2_P + ((p == 2) ? 16384u : 0u));
                    uint64_t vd = mk_desc(Vst + ((p == 1) ? 16384u : 0u));
                    #pragma unroll
                    for (int k = 0; k < 4; k++) {
                        t5_mma_f16_ss(tmem + 128, pd + k*2, vd + k*2, IDESC_PV,
                                      (t == 0 && first) ? 0u : 1u);
                        first = false;
                    }
                }
                t5_commit(smb + MB_KVE + s*8);
                t5_commit(smb + MB_PF);
                if (t == nt - 1) t5_commit(smb + MB_OR);
            }
        }
        sLi[row] = 1.f / l;
    }

    mbar_wait(smb + MB_OR, 0);
    t5_fence_after();
    __syncthreads();

    {
        const int row = ((warp & 3) << 5) | lane;
        const int dbase = (warp >> 2) * 64;
        float li = sLi[row];
        float ov[64];
        ldtm_x32((uint32_t*)ov, tmem + 128 + dbase);
        ldtm_x32((uint32_t*)(ov + 32), tmem + 128 + dbase + 32);
        t5_wait_ld(); t5_fence_before();
        const int R = b*SS + qt*128 + row;
        const int tile = R >> 7;
        #pragma unroll
        for (int j = 0; j < 64; j += 2) {
            int Ccol = h*128 + dbase + j;
            int chunk = Ccol >> 6, cin = Ccol & 63;
            uint32_t sw = swz((uint32_t)(row*128 + cin*2));
            size_t idx = ((size_t)(tile*32 + chunk) << 13) + (sw >> 1);
            float v0 = ov[j] * li, v1 = ov[j+1] * li;
            __nv_bfloat16 h0 = __float2bfloat16(v0), h1 = __float2bfloat16(v1);
            __nv_bfloat16 l0 = __float2bfloat16(v0 - __bfloat162float(h0));
            __nv_bfloat16 l1 = __float2bfloat16(v1 - __bfloat162float(h1));
            *(__nv_bfloat162*)&OHh[idx] = __halves2bfloat162(h0, h1);
            *(__nv_bfloat162*)&OHl[idx] = __halves2bfloat162(l0, l1);
        }
    }
    __syncthreads();
    if (tid == 0) {
        mbar_inval(smb + MB_KVF + 0); mbar_inval(smb + MB_KVF + 8);
        mbar_inval(smb + MB_KVE + 0); mbar_inval(smb + MB_KVE + 8);
        mbar_inval(smb + MB_SD + 0);  mbar_inval(smb + MB_SD + 8);
        mbar_inval(smb + MB_PR); mbar_inval(smb + MB_PF); mbar_inval(smb + MB_OR);
        mbar_inval(smb + MB_QL);
    }
    if (warp == 0) t5_dealloc(tmem, 512);
#endif
}

// ---------------- launch ----------------
extern "C" void kernel_launch(void* const* d_in, const int* in_sizes, int n_in,
                              void* d_out, int out_size)
{
    const float* x      = (const float*)d_in[0];
    const float* wq     = (const float*)d_in[1];
    const float* wkv_a  = (const float*)d_in[2];
    const float* kvw    = (const float*)d_in[3];
    const float* wkv_b  = (const float*)d_in[4];
    const float* wo     = (const float*)d_in[5];
    const float* cosp   = (const float*)d_in[6];
    const float* sinp   = (const float*)d_in[7];
    float* out = (float*)d_out;

    float *KV, *V;
    __nv_bfloat16 *Xh, *Xl, *WQh, *WQl, *WAh, *WAl, *WBkh, *WBkl, *WBvh, *WBvl, *WOh, *WOl;
    __nv_bfloat16 *CKVh, *CKVl, *OHh, *OHl, *Qp, *Kp, *Vp;
    cudaGetSymbolAddress((void**)&KV,   g_KV);
    cudaGetSymbolAddress((void**)&V,    g_V);
    cudaGetSymbolAddress((void**)&Xh,   g_Xh);   cudaGetSymbolAddress((void**)&Xl,   g_Xl);
    cudaGetSymbolAddress((void**)&WQh,  g_WQh);  cudaGetSymbolAddress((void**)&WQl,  g_WQl);
    cudaGetSymbolAddress((void**)&WAh,  g_WAh);  cudaGetSymbolAddress((void**)&WAl,  g_WAl);
    cudaGetSymbolAddress((void**)&WBkh, g_WBkh); cudaGetSymbolAddress((void**)&WBkl, g_WBkl);
    cudaGetSymbolAddress((void**)&WBvh, g_WBvh); cudaGetSymbolAddress((void**)&WBvl, g_WBvl);
    cudaGetSymbolAddress((void**)&WOh,  g_WOh);  cudaGetSymbolAddress((void**)&WOl,  g_WOl);
    cudaGetSymbolAddress((void**)&CKVh, g_CKVh); cudaGetSymbolAddress((void**)&CKVl, g_CKVl);
    cudaGetSymbolAddress((void**)&OHh,  g_OHh);  cudaGetSymbolAddress((void**)&OHl,  g_OHl);
    cudaGetSymbolAddress((void**)&Qp,   g_Qp);
    cudaGetSymbolAddress((void**)&Kp,   g_Kp);   cudaGetSymbolAddress((void**)&Vp,   g_Vp);

    cudaFuncSetAttribute(gemm_t5, cudaFuncAttributeMaxDynamicSharedMemorySize, GEMM_SMEM);
    cudaFuncSetAttribute(attn_t5, cudaFuncAttributeMaxDynamicSharedMemorySize, A2_SMEM);

    const int BIGGRP = 1 << 30;

    {
        size_t n;
        n = (size_t)BS*DIM;     split_A_kernel<<<(int)((n+255)/256), 256>>>(x, Xh, Xl, DIM, 32);
        n = (size_t)12*256*DIM; split_B_kernel<<<(int)((n+255)/256), 256>>>(wq, WQh, WQl, HH*QK, DIM, BIGGRP, 0, 0, n);
        n = (size_t)3*256*DIM;  split_B_kernel<<<(int)((n+255)/256), 256>>>(wkv_a, WAh, WAl, KVR+ROPE, DIM, BIGGRP, 0, 0, n);
        n = (size_t)8*256*KVR;  split_B_kernel<<<(int)((n+255)/256), 256>>>(wkv_b, WBkh, WBkl, HH*NOPE, KVR, 128, 256, 0, n);
        n = (size_t)8*256*KVR;  split_B_kernel<<<(int)((n+255)/256), 256>>>(wkv_b, WBvh, WBvl, HH*VDIM, KVR, 128, 256, 128, n);
        n = (size_t)8*256*DIM;  split_B_kernel<<<(int)((n+255)/256), 256>>>(wo, WOh, WOl, DIM, DIM, BIGGRP, 0, 0, n);
    }

    // 1. Q = X @ Wq^T -> Qp panels (fused rope)
    gemm_t5<<<dim3(12, 32), 128, GEMM_SMEM>>>(Xh, Xl, WQh, WQl, nullptr, Qp, HH*QK, 32, 1, cosp, sinp);
    // 2. KV = X @ Wkv_a^T (fp32)
    gemm_t5<<<dim3(3, 32), 128, GEMM_SMEM>>>(Xh, Xl, WAh, WAl, KV, nullptr, KVR+ROPE, 32, 0, nullptr, nullptr);
    // 3. rmsnorm -> CKV panels; rope(k_pe) -> Kp chunk 2
    kv_post_kernel<<<BS, 128>>>(KV, kvw, cosp, sinp, CKVh, CKVl, Kp);
    // 4. k_nope = CKV @ wb_k^T -> Kp chunks 0/1
    gemm_t5<<<dim3(8, 32), 128, GEMM_SMEM>>>(CKVh, CKVl, WBkh, WBkl, nullptr, Kp, HH*NOPE, 8, 2, nullptr, nullptr);
    // 5. v = CKV @ wb_v^T (fp32)
    gemm_t5<<<dim3(8, 32), 128, GEMM_SMEM>>>(CKVh, CKVl, WBvh, WBvl, V, nullptr, HH*VDIM, 8, 0, nullptr, nullptr);
    // 5b. V panels (transpose)
    vpanel_kernel<<<1024, 256>>>(V, Vp);
    // 6. tcgen05 flash attention -> OH panels
    attn_t5<<<dim3(16, HH, BB), 256, A2_SMEM>>>(Qp, Kp, Vp, OHh, OHl);
    // 7. out = OH @ wo^T (fp32)
    gemm_t5<<<dim3(8, 32), 128, GEMM_SMEM>>>(OHh, OHl, WOh, WOl, out, nullptr, DIM, 32, 0, nullptr, nullptr);
}

// round 17
// speedup vs baseline: 1.0344x; 1.0344x over previous
#include <cuda_runtime.h>
#include <cuda_bf16.h>
#include <math.h>
#include <stdint.h>

#if defined(__CUDA_ARCH__) && (defined(__CUDA_ARCH_FEAT_SM103_ALL) || (defined(__CUDA_ARCH_SPECIFIC__) && (__CUDA_ARCH_SPECIFIC__ == 1030)))
#define T5_OK 1
#else
#define T5_OK 0
#endif

#define BB 2
#define SS 2048
#define DIM 2048
#define HH 16
#define KVR 512
#define NOPE 128
#define ROPE 64
#define VDIM 128
#define QK 192
#define BS (BB*SS)
#define SCALE_C 0.07216878364870322f

__device__ float g_KV [(size_t)BS * (KVR+ROPE)];
__device__ float g_V  [(size_t)BS * (HH*VDIM)];

#define APAN 8192
#define BPAN 16384
__device__ __align__(1024) __nv_bfloat16 g_Xh [(size_t)32*32*APAN],  g_Xl [(size_t)32*32*APAN];
__device__ __align__(1024) __nv_bfloat16 g_WQh[(size_t)12*32*BPAN],  g_WQl[(size_t)12*32*BPAN];
__device__ __align__(1024) __nv_bfloat16 g_WAh[(size_t)3*32*BPAN],   g_WAl[(size_t)3*32*BPAN];
__device__ __align__(1024) __nv_bfloat16 g_WBkh[(size_t)8*8*BPAN],   g_WBkl[(size_t)8*8*BPAN];
__device__ __align__(1024) __nv_bfloat16 g_WBvh[(size_t)8*8*BPAN],   g_WBvl[(size_t)8*8*BPAN];
__device__ __align__(1024) __nv_bfloat16 g_WOh[(size_t)8*32*BPAN],   g_WOl[(size_t)8*32*BPAN];
__device__ __align__(1024) __nv_bfloat16 g_CKVh[(size_t)32*8*APAN],  g_CKVl[(size_t)32*8*APAN];
__device__ __align__(1024) __nv_bfloat16 g_OHh[(size_t)32*32*APAN],  g_OHl[(size_t)32*32*APAN];
__device__ __align__(1024) __nv_bfloat16 g_Qp [(size_t)512*49152];
__device__ __align__(1024) __nv_bfloat16 g_Kp [(size_t)1024*24576];
__device__ __align__(1024) __nv_bfloat16 g_Vp [(size_t)1024*16384];

__device__ __forceinline__ uint32_t swz(uint32_t off) { return off ^ ((off >> 3) & 0x70); }

#if T5_OK
__device__ __forceinline__ uint32_t smem_u32(const void* p) {
    uint32_t a;
    asm("{ .reg .u64 t; cvta.to.shared.u64 t, %1; cvt.u32.u64 %0, t; }" : "=r"(a) : "l"(p));
    return a;
}
__device__ __forceinline__ uint32_t elect_one() {
    uint32_t p;
    asm volatile("{\n\t.reg .pred p;\n\telect.sync _|p, 0xFFFFFFFF;\n\tselp.b32 %0, 1, 0, p;\n\t}" : "=r"(p));
    return p;
}
__device__ __forceinline__ void mbar_init(uint32_t a, uint32_t n) {
    asm volatile("mbarrier.init.shared.b64 [%0], %1;" :: "r"(a), "r"(n) : "memory");
}
__device__ __forceinline__ void mbar_inval(uint32_t a) {
    asm volatile("mbarrier.inval.shared.b64 [%0];" :: "r"(a) : "memory");
}
__device__ __forceinline__ void mbar_arrive(uint32_t a) {
    asm volatile("mbarrier.arrive.shared.b64 _, [%0];" :: "r"(a) : "memory");
}
__device__ __forceinline__ void mbar_expect_tx(uint32_t a, uint32_t bytes) {
    asm volatile("mbarrier.arrive.expect_tx.shared.b64 _, [%0], %1;" :: "r"(a), "r"(bytes) : "memory");
}
__device__ __forceinline__ void mbar_wait(uint32_t a, uint32_t parity) {
    asm volatile(
        "{\n\t.reg .pred P;\n\t"
        "W_%=:\n\t"
        "mbarrier.try_wait.parity.acquire.cta.shared::cta.b64 P, [%0], %1, 0x989680;\n\t"
        "@P bra.uni D_%=;\n\t"
        "bra.uni W_%=;\n\t"
        "D_%=:\n\t}"
        :: "r"(a), "r"(parity) : "memory");
}
__device__ __forceinline__ void bulk_g2s(uint32_t dst, const void* src, uint32_t bytes, uint32_t mbar) {
    asm volatile(
        "cp.async.bulk.shared::cta.global.mbarrier::complete_tx::bytes [%0], [%1], %2, [%3];"
        :: "r"(dst), "l"(src), "r"(bytes), "r"(mbar) : "memory");
}
__device__ __forceinline__ void t5_alloc(uint32_t smem_res, uint32_t ncols) {
    asm volatile("tcgen05.alloc.cta_group::1.sync.aligned.shared::cta.b32 [%0], %1;"
                 :: "r"(smem_res), "r"(ncols) : "memory");
}
__device__ __forceinline__ void t5_dealloc(uint32_t tmem, uint32_t ncols) {
    asm volatile("tcgen05.dealloc.cta_group::1.sync.aligned.b32 %0, %1;" :: "r"(tmem), "r"(ncols));
}
__device__ __forceinline__ void t5_commit(uint32_t mbar) {
    asm volatile("tcgen05.commit.cta_group::1.mbarrier::arrive::one.shared::cluster.b64 [%0];"
                 :: "r"(mbar) : "memory");
}
__device__ __forceinline__ void t5_fence_after()  { asm volatile("tcgen05.fence::after_thread_sync;" ::: "memory"); }
__device__ __forceinline__ void t5_fence_before() { asm volatile("tcgen05.fence::before_thread_sync;" ::: "memory"); }
__device__ __forceinline__ void t5_wait_ld()      { asm volatile("tcgen05.wait::ld.sync.aligned;" ::: "memory"); }
__device__ __forceinline__ void t5_wait_st()      { asm volatile("tcgen05.wait::st.sync.aligned;" ::: "memory"); }
__device__ __forceinline__ void fence_pa()        { asm volatile("fence.proxy.async.shared::cta;" ::: "memory"); }
__device__ __forceinline__ void t5_mma_f16_ss(uint32_t d, uint64_t ad, uint64_t bd,
                                              uint32_t idesc, uint32_t en) {
    asm volatile(
        "{\n\t.reg .pred p;\n\t"
        "setp.ne.u32 p, %4, 0;\n\t"
        "tcgen05.mma.cta_group::1.kind::f16 [%0], %1, %2, %3, {%5,%5,%5,%5}, p;\n\t}"
        :: "r"(d), "l"(ad), "l"(bd), "r"(idesc), "r"(en), "r"(0u) : "memory");
}
__device__ __forceinline__ void t5_mma_f16_ts(uint32_t d, uint32_t at, uint64_t bd,
                                              uint32_t idesc, uint32_t en) {
    asm volatile(
        "{\n\t.reg .pred p;\n\t"
        "setp.ne.u32 p, %4, 0;\n\t"
        "tcgen05.mma.cta_group::1.kind::f16 [%0], [%1], %2, %3, {%5,%5,%5,%5}, p;\n\t}"
        :: "r"(d), "r"(at), "l"(bd), "r"(idesc), "r"(en), "r"(0u) : "memory");
}
__device__ __forceinline__ void ldtm_x32(uint32_t* d, uint32_t addr) {
    asm volatile(
        "tcgen05.ld.sync.aligned.32x32b.x32.b32 "
        "{%0, %1, %2, %3, %4, %5, %6, %7, "
        " %8, %9, %10, %11, %12, %13, %14, %15, "
        " %16, %17, %18, %19, %20, %21, %22, %23, "
        " %24, %25, %26, %27, %28, %29, %30, %31}, [%32];"
        : "=r"(d[0]),  "=r"(d[1]),  "=r"(d[2]),  "=r"(d[3]),
          "=r"(d[4]),  "=r"(d[5]),  "=r"(d[6]),  "=r"(d[7]),
          "=r"(d[8]),  "=r"(d[9]),  "=r"(d[10]), "=r"(d[11]),
          "=r"(d[12]), "=r"(d[13]), "=r"(d[14]), "=r"(d[15]),
          "=r"(d[16]), "=r"(d[17]), "=r"(d[18]), "=r"(d[19]),
          "=r"(d[20]), "=r"(d[21]), "=r"(d[22]), "=r"(d[23]),
          "=r"(d[24]), "=r"(d[25]), "=r"(d[26]), "=r"(d[27]),
          "=r"(d[28]), "=r"(d[29]), "=r"(d[30]), "=r"(d[31])
        : "r"(addr));
}
__device__ __forceinline__ void sttm_x32(uint32_t addr, const uint32_t* r) {
    asm volatile(
        "tcgen05.st.sync.aligned.32x32b.x32.b32 [%0], "
        "{%1, %2, %3, %4, %5, %6, %7, %8, "
        " %9, %10, %11, %12, %13, %14, %15, %16, "
        " %17, %18, %19, %20, %21, %22, %23, %24, "
        " %25, %26, %27, %28, %29, %30, %31, %32};"
        :: "r"(addr),
           "r"(r[0]),  "r"(r[1]),  "r"(r[2]),  "r"(r[3]),
           "r"(r[4]),  "r"(r[5]),  "r"(r[6]),  "r"(r[7]),
           "r"(r[8]),  "r"(r[9]),  "r"(r[10]), "r"(r[11]),
           "r"(r[12]), "r"(r[13]), "r"(r[14]), "r"(r[15]),
           "r"(r[16]), "r"(r[17]), "r"(r[18]), "r"(r[19]),
           "r"(r[20]), "r"(r[21]), "r"(r[22]), "r"(r[23]),
           "r"(r[24]), "r"(r[25]), "r"(r[26]), "r"(r[27]),
           "r"(r[28]), "r"(r[29]), "r"(r[30]), "r"(r[31])
        : "memory");
}
static __device__ __forceinline__ uint64_t mk_desc(uint32_t addr) {
    const uint64_t base = (uint64_t(2) << 61) | (uint64_t(1) << 46)
                        | (uint64_t(64) << 32) | (uint64_t(1) << 16);
    return base | ((uint64_t)(addr >> 4) & 0x3FFF);
}
#define T5_IDESC ((1u<<4)|(1u<<7)|(1u<<10)|(32u<<17)|(8u<<24))
#define IDESC_QK ((1u<<4)|(1u<<7)|(1u<<10)|(8u<<17)|(8u<<24))
#define IDESC_PV ((1u<<4)|(1u<<7)|(1u<<10)|(16u<<17)|(8u<<24))
#endif

// ---------------- split kernels ----------------
__global__ void split_A_kernel(const float* __restrict__ src,
                               __nv_bfloat16* __restrict__ dh, __nv_bfloat16* __restrict__ dl,
                               int K, int nchunks)
{
#if T5_OK
    size_t i = (size_t)blockIdx.x * 256 + threadIdx.x;
    if (i >= (size_t)BS * K) return;
    int row = (int)(i / K), k = (int)(i % K);
    float v = src[i];
    int tile = row >> 7, rin = row & 127, chunk = k >> 6, cin = k & 63;
    uint32_t sw = swz((uint32_t)(rin * 128 + cin * 2));
    size_t idx = ((size_t)(tile * nchunks + chunk) << 13) + (sw >> 1);
    __nv_bfloat16 h = __float2bfloat16(v);
    dh[idx] = h;
    dl[idx] = __float2bfloat16(v - __bfloat162float(h));
#endif
}

__global__ void split_B_kernel(const float* __restrict__ src,
                               __nv_bfloat16* __restrict__ dh, __nv_bfloat16* __restrict__ dl,
                               int Nrows, int K, int group, int gstride, int gbase, size_t total)
{
#if T5_OK
    size_t i = (size_t)blockIdx.x * 256 + threadIdx.x;
    if (i >= total) return;
    int n = (int)(i / K), k = (int)(i % K);
    float v = 0.f;
    if (n < Nrows) {
        int br = gbase + (n / group) * gstride + (n % group);
        v = src[(size_t)br * K + k];
    }
    int tile = n >> 8, rin = n & 255, chunk = k >> 6, cin = k & 63;
    int nchunks = K >> 6;
    uint32_t sw = swz((uint32_t)(rin * 128 + cin * 2));
    size_t idx = ((size_t)(tile * nchunks + chunk) << 14) + (sw >> 1);
    __nv_bfloat16 h = __float2bfloat16(v);
    dh[idx] = h;
    dl[idx] = __float2bfloat16(v - __bfloat162float(h));
#endif
}

// ---------------- tcgen05 bf16x3 GEMM (R11-proven core + epilogue modes) ----------------
#define SM_TMPTR 0
#define SM_FULL0 16
#define SM_FREE0 32
#define SM_DONE  48
#define SM_STG0  1024
#define STG_BYTES 98304
#define OFF_AH 0
#define OFF_AL 16384
#define OFF_BH 32768
#define OFF_BL 65536
#define GEMM_SMEM (1024 + 2*STG_BYTES)

__global__ __launch_bounds__(128, 1)
void gemm_t5(const __nv_bfloat16* __restrict__ Ah, const __nv_bfloat16* __restrict__ Al,
             const __nv_bfloat16* __restrict__ Bh, const __nv_bfloat16* __restrict__ Bl,
             float* __restrict__ C, __nv_bfloat16* __restrict__ pan,
             int N, int nchunks, int mode,
             const float* __restrict__ COS, const float* __restrict__ SIN)
{
#if T5_OK
    extern __shared__ __align__(1024) char smraw[];
    const uint32_t smb = smem_u32(smraw);
    const int tid  = threadIdx.x;
    const int warp = tid >> 5;
    const int lane = tid & 31;
    const int tile_n = blockIdx.x;
    const int tile_m = blockIdx.y;

    if (tid == 0) {
        mbar_init(smb + SM_FULL0 + 0, 1);
        mbar_init(smb + SM_FULL0 + 8, 1);
        mbar_init(smb + SM_FREE0 + 0, 1);
        mbar_init(smb + SM_FREE0 + 8, 1);
        mbar_init(smb + SM_DONE, 1);
    }
    if (warp == 1) t5_alloc(smb + SM_TMPTR, 512);
    __syncthreads();
    uint32_t tmem;
    asm volatile("ld.shared.b32 %0, [%1];" : "=r"(tmem) : "r"(smb + SM_TMPTR));

    if (warp == 0) {
        if (elect_one()) {
            uint32_t pph = 1;
            const size_t abase = (size_t)tile_m * nchunks;
            const size_t bbase = (size_t)tile_n * nchunks;
            for (int c = 0; c < nchunks; c++) {
                int s = c & 1;
                uint32_t stg = smb + SM_STG0 + s * STG_BYTES;
                mbar_wait(smb + SM_FREE0 + s * 8, pph);
                mbar_expect_tx(smb + SM_FULL0 + s * 8, STG_BYTES);
                bulk_g2s(stg + OFF_AH, Ah + (abase + c) * APAN, 16384, smb + SM_FULL0 + s * 8);
                bulk_g2s(stg + OFF_AL, Al + (abase + c) * APAN, 16384, smb + SM_FULL0 + s * 8);
                bulk_g2s(stg + OFF_BH, Bh + (bbase + c) * BPAN, 32768, smb + SM_FULL0 + s * 8);
                bulk_g2s(stg + OFF_BL, Bl + (bbase + c) * BPAN, 32768, smb + SM_FULL0 + s * 8);
                if (s == 1) pph ^= 1;
            }
        }
    }
    if (warp == 1) {
        if (elect_one()) {
            uint32_t cph = 0;
            for (int c = 0; c < nchunks; c++) {
                int s = c & 1;
                uint32_t stg = smb + SM_STG0 + s * STG_BYTES;
                mbar_wait(smb + SM_FULL0 + s * 8, cph);
                uint64_t ahd = mk_desc(stg + OFF_AH);
                uint64_t ald = mk_desc(stg + OFF_AL);
                uint64_t bhd = mk_desc(stg + OFF_BH);
                uint64_t bld = mk_desc(stg + OFF_BL);
                uint64_t ads[3] = {ahd, ahd, ald};
                uint64_t bds[3] = {bhd, bld, bhd};
                #pragma unroll
                for (int p = 0; p < 3; p++) {
                    #pragma unroll
                    for (int k = 0; k < 4; k++) {
                        uint32_t en = (c | p | k) ? 1u : 0u;
                        t5_mma_f16_ss(tmem, ads[p] + k * 2, bds[p] + k * 2, T5_IDESC, en);
                    }
                }
                t5_commit(smb + SM_FREE0 + s * 8);
                if (c == nchunks - 1) t5_commit(smb + SM_DONE);
                if (s == 1) cph ^= 1;
            }
        }
    }

    mbar_wait(smb + SM_DONE, 0);
    t5_fence_after();

    const int gr = (tile_m << 7) + (warp << 5) + lane;
    #pragma unroll 1
    for (int cb = 0; cb < 8; cb++) {
        uint32_t d[32];
        ldtm_x32(d, tmem + cb * 32);
        t5_wait_ld();
        int gc0 = (tile_n << 8) + (cb << 5);
        if (mode == 0) {
            float* cp = C + (size_t)gr * N + gc0;
            #pragma unroll
            for (int j = 0; j < 32; j += 4) {
                if (gc0 + j < N)
                    *(float4*)(cp + j) = make_float4(__uint_as_float(d[j]),   __uint_as_float(d[j+1]),
                                                     __uint_as_float(d[j+2]), __uint_as_float(d[j+3]));
            }
        } else if (mode == 1) {
            int hh = gc0 / 192;
            int dd0 = gc0 % 192;
            int ch = dd0 >> 6;
            int cin0 = dd0 & 63;
            float vals[32];
            #pragma unroll
            for (int j = 0; j < 32; j++) vals[j] = __uint_as_float(d[j]);
            if (dd0 >= 128) {
                int spos = gr & (SS - 1);
                int i0 = (dd0 - 128) >> 1;
                #pragma unroll
                for (int jp = 0; jp < 16; jp++) {
                    float c  = COS[spos * 32 + i0 + jp];
                    float sn = SIN[spos * 32 + i0 + jp];
                    float xe = vals[2*jp], xo = vals[2*jp + 1];
                    vals[2*jp]     = xe * c - xo * sn;
                    vals[2*jp + 1] = xe * sn + xo * c;
                }
            }
            int bh = (gr >> 11) * 16 + hh;
            int qt = (gr >> 7) & 15;
            int rin = gr & 127;
            size_t pb = (size_t)(bh * 16 + qt) * 49152;
            #pragma unroll
            for (int j = 0; j < 32; j += 2) {
                uint32_t sw = swz((uint32_t)(rin * 128 + (cin0 + j) * 2));
                float v0 = vals[j], v1 = vals[j+1];
                __nv_bfloat16 h0 = __float2bfloat16(v0), h1 = __float2bfloat16(v1);
                __nv_bfloat16 l0 = __float2bfloat16(v0 - __bfloat162float(h0));
                __nv_bfloat16 l1 = __float2bfloat16(v1 - __bfloat162float(h1));
                *(__nv_bfloat162*)&pan[pb + ch * 8192 + (sw >> 1)]         = __halves2bfloat162(h0, h1);
                *(__nv_bfloat162*)&pan[pb + 24576 + ch * 8192 + (sw >> 1)] = __halves2bfloat162(l0, l1);
            }
        } else {
            int hh = gc0 >> 7;
            int dd0 = gc0 & 127;
            int ch = dd0 >> 6;
            int cin0 = dd0 & 63;
            int b = gr >> 11, t = gr & (SS - 1);
            int kt = t >> 6, rin = t & 63;
            size_t pb = (size_t)((b * 16 + hh) * 32 + kt) * 24576;
            #pragma unroll
            for (int j = 0; j < 32; j += 2) {
                uint32_t sw = swz((uint32_t)(rin * 128 + (cin0 + j) * 2));
                float v0 = __uint_as_float(d[j]), v1 = __uint_as_float(d[j+1]);
                __nv_bfloat16 h0 = __float2bfloat16(v0), h1 = __float2bfloat16(v1);
                __nv_bfloat16 l0 = __float2bfloat16(v0 - __bfloat162float(h0));
                __nv_bfloat16 l1 = __float2bfloat16(v1 - __bfloat162float(h1));
                *(__nv_bfloat162*)&pan[pb + ch * 4096 + (sw >> 1)]         = __halves2bfloat162(h0, h1);
                *(__nv_bfloat162*)&pan[pb + 12288 + ch * 4096 + (sw >> 1)] = __halves2bfloat162(l0, l1);
            }
        }
    }

    __syncthreads();
    if (tid == 0) {
        mbar_inval(smb + SM_FULL0 + 0); mbar_inval(smb + SM_FULL0 + 8);
        mbar_inval(smb + SM_FREE0 + 0); mbar_inval(smb + SM_FREE0 + 8);
        mbar_inval(smb + SM_DONE);
    }
    if (warp == 1) t5_dealloc(tmem, 512);
#endif
}

// ---------------- KV post: rmsnorm -> CKV panels, rope(k_pe) -> Kp chunk 2 ----------------
__global__ void kv_post_kernel(const float* __restrict__ KV,
                               const float* __restrict__ W,
                               const float* __restrict__ COS,
                               const float* __restrict__ SIN,
                               __nv_bfloat16* __restrict__ CKVh,
                               __nv_bfloat16* __restrict__ CKVl,
                               __nv_bfloat16* __restrict__ Kp)
{
#if T5_OK
    __shared__ float red[4];
    __shared__ float rs_s;
    const int m = blockIdx.x;
    const int tid = threadIdx.x;
    const float* row = KV + (size_t)m * (KVR+ROPE);

    float ss = 0.f;
    for (int c = tid; c < KVR; c += 128) { float v = row[c]; ss += v * v; }
    #pragma unroll
    for (int o = 16; o; o >>= 1) ss += __shfl_xor_sync(0xffffffffu, ss, o);
    if ((tid & 31) == 0) red[tid >> 5] = ss;
    __syncthreads();
    if (tid == 0) {
        float t = red[0] + red[1] + red[2] + red[3];
        rs_s = rsqrtf(t / (float)KVR + 1e-6f);
    }
    __syncthreads();
    float rs = rs_s;
    const int tile = m >> 7, rin = m & 127;
    for (int c = tid; c < KVR; c += 128) {
        float v = row[c] * rs * W[c];
        int chunk = c >> 6, cin = c & 63;
        uint32_t sw = swz((uint32_t)(rin * 128 + cin * 2));
        size_t idx = ((size_t)(tile * 8 + chunk) << 13) + (sw >> 1);
        __nv_bfloat16 h = __float2bfloat16(v);
        CKVh[idx] = h;
        CKVl[idx] = __float2bfloat16(v - __bfloat162float(h));
    }
    if (tid < 32) {
        int i = tid;
        int s = m & (SS - 1);
        float xe = row[KVR + 2*i], xo = row[KVR + 2*i + 1];
        float c  = COS[s*32 + i], sn = SIN[s*32 + i];
        float ye = xe*c - xo*sn;
        float yo = xe*sn + xo*c;
        __nv_bfloat16 h0 = __float2bfloat16(ye), h1 = __float2bfloat16(yo);
        __nv_bfloat16 l0 = __float2bfloat16(ye - __bfloat162float(h0));
        __nv_bfloat16 l1 = __float2bfloat16(yo - __bfloat162float(h1));
        __nv_bfloat162 ph = __halves2bfloat162(h0, h1);
        __nv_bfloat162 pl = __halves2bfloat162(l0, l1);
        int b = m >> 11, t = m & (SS - 1);
        int kt = t >> 6, krin = t & 63;
        uint32_t sw = swz((uint32_t)(krin * 128 + (2*i) * 2));
        #pragma unroll 1
        for (int h = 0; h < HH; h++) {
            size_t pb = (size_t)((b * 16 + h) * 32 + kt) * 24576;
            *(__nv_bfloat162*)&Kp[pb + 2*4096 + (sw >> 1)]         = ph;
            *(__nv_bfloat162*)&Kp[pb + 12288 + 2*4096 + (sw >> 1)] = pl;
        }
    }
#endif
}

// ---------------- V panel builder (transpose) ----------------
__global__ __launch_bounds__(256)
void vpanel_kernel(const float* __restrict__ V, __nv_bfloat16* __restrict__ Vp)
{
#if T5_OK
    __shared__ float sm[64][129];
    int blk = blockIdx.x;
    int bh = blk >> 5, kt = blk & 31;
    int b = bh >> 4, h = bh & 15;
    for (int i = threadIdx.x; i < 8192; i += 256) {
        int tt = i >> 7, d = i & 127;
        sm[tt][d] = V[(size_t)(b*SS + kt*64 + tt)*2048 + h*128 + d];
    }
    __syncthreads();
    size_t base = (size_t)blk * 16384;
    for (int i = threadIdx.x; i < 4096; i += 256) {
        int d = i >> 5, tp = (i & 31)*2;
        float v0 = sm[tp][d], v1 = sm[tp+1][d];
        uint32_t sw = swz((uint32_t)(d*128 + tp*2));
        __nv_bfloat16 h0 = __float2bfloat16(v0), h1 = __float2bfloat16(v1);
        __nv_bfloat16 l0 = __float2bfloat16(v0 - __bfloat162float(h0));
        __nv_bfloat16 l1 = __float2bfloat16(v1 - __bfloat162float(h1));
        *(__nv_bfloat162*)&Vp[base + (sw >> 1)]        = __halves2bfloat162(h0, h1);
        *(__nv_bfloat162*)&Vp[base + 8192 + (sw >> 1)] = __halves2bfloat162(l0, l1);
    }
#endif
}

// ---------------- tcgen05 flash attention (QK(t+1) issued AFTER PV(t)) ----------------
#define MB_KVF 0
#define MB_KVE 16
#define MB_SD  32
#define MB_PR  48
#define MB_PF  56
#define MB_OR  64
#define MB_QL  72
#define SM_TM  80
#define SM_LI  128
#define A2_K0  1024
#define A2_K1  50176
#define A2_V0  99328
#define A2_V1  132096
#define A2_P   164864
#define A2_SMEM 197632

__global__ __launch_bounds__(256, 1)
void attn_t5(const __nv_bfloat16* __restrict__ Qp, const __nv_bfloat16* __restrict__ Kp,
             const __nv_bfloat16* __restrict__ Vp,
             __nv_bfloat16* __restrict__ OHh, __nv_bfloat16* __restrict__ OHl)
{
#if T5_OK
    extern __shared__ __align__(1024) char smraw[];
    const uint32_t smb = smem_u32(smraw);
    float* sLi = (float*)(smraw + SM_LI);
    const int tid = threadIdx.x, warp = tid >> 5, lane = tid & 31;
    const int qt = 15 - blockIdx.x, h = blockIdx.y, b = blockIdx.z;
    const int bh = b*16 + h;
    const int nt = 2*qt + 2;

    if (tid == 0) {
        mbar_init(smb + MB_KVF + 0, 1); mbar_init(smb + MB_KVF + 8, 1);
        mbar_init(smb + MB_KVE + 0, 1); mbar_init(smb + MB_KVE + 8, 1);
        mbar_init(smb + MB_SD  + 0, 1); mbar_init(smb + MB_SD  + 8, 1);
        mbar_init(smb + MB_PR, 4);
        mbar_init(smb + MB_PF, 1);
        mbar_init(smb + MB_OR, 1);
        mbar_init(smb + MB_QL, 1);
    }
    if (warp == 0) t5_alloc(smb + SM_TM, 512);
    __syncthreads();
    uint32_t tmem;
    asm volatile("ld.shared.b32 %0, [%1];" : "=r"(tmem) : "r"(smb + SM_TM));
    uint32_t amI = (warp == 0) ? elect_one() : 0;
    uint32_t amP = (warp == 4) ? elect_one() : 0;

    // Q panel -> smem (bulk) -> TMEM
    if (amI) {
        mbar_expect_tx(smb + MB_QL, 98304);
        bulk_g2s(smb + A2_K0, Qp + (size_t)(bh*16 + qt) * 49152, 98304, smb + MB_QL);
    }
    mbar_wait(smb + MB_QL, 0);
    if (warp < 4) {
        int row = (warp << 5) | lane;
        uint32_t woff = (uint32_t)warp << 21;
        #pragma unroll 1
        for (int c3 = 0; c3 < 3; c3++) {
            uint32_t hi[32], lo[32];
            #pragma unroll
            for (int j = 0; j < 32; j++) {
                uint32_t sw = swz((uint32_t)(row*128 + j*4));
                hi[j] = *(uint32_t*)(smraw + A2_K0 + c3*16384 + sw);
                lo[j] = *(uint32_t*)(smraw + A2_K0 + 49152 + c3*16384 + sw);
            }
            sttm_x32(tmem + 256 + c3*32 + woff, hi);
            sttm_x32(tmem + 352 + c3*32 + woff, lo);
        }
        t5_wait_st();
    }
    t5_fence_before();
    __syncthreads();

    if (amP) {
        for (int t = 0; t < nt; t++) {
            int s = t & 1;
            if (t >= 2) mbar_wait(smb + MB_KVE + s*8, ((t - 2) >> 1) & 1);
            mbar_expect_tx(smb + MB_KVF + s*8, 81920);
            bulk_g2s(smb + (s ? A2_K1 : A2_K0), Kp + (size_t)(bh*32 + t)*24576, 49152, smb + MB_KVF + s*8);
            bulk_g2s(smb + (s ? A2_V1 : A2_V0), Vp + (size_t)(bh*32 + t)*16384, 32768, smb + MB_KVF + s*8);
        }
    }

    if (warp < 4) {
        const int row = (warp << 5) | lane;
        const int grow = qt*128 + row;
        float l = 0.f;
        uint32_t pfp = 0;
        // prologue: issue QK(0)
        if (amI) {
            mbar_wait(smb + MB_KVF + 0, 0);
            bool first = true;
            #pragma unroll
            for (int p = 0; p < 3; p++) {
                uint32_t ab = (p == 2) ? 352u : 256u;
                uint32_t bo = (p == 1) ? 24576u : 0u;
                #pragma unroll
                for (int ks = 0; ks < 12; ks++) {
                    uint64_t kd = mk_desc(smb + A2_K0 + bo + (ks >> 2)*8192) + (ks & 3)*2;
                    t5_mma_f16_ts(tmem, tmem + ab + ks*8, kd, IDESC_QK, first ? 0u : 1u);
                    first = false;
                }
            }
            t5_commit(smb + MB_SD + 0);
        }
        for (int t = 0; t < nt; t++) {
            const int s = t & 1;
            const uint32_t Sb = tmem + s*64;
            mbar_wait(smb + MB_SD + s*8, (t >> 1) & 1);
            t5_fence_after();
            float sv[64];
            ldtm_x32((uint32_t*)sv, Sb);
            ldtm_x32((uint32_t*)(sv + 32), Sb + 32);
            t5_wait_ld(); t5_fence_before();
            const int t0 = t*64;
            #pragma unroll
            for (int j = 0; j < 64; j++) {
                float e = (t0 + j > grow) ? 0.f : __expf(sv[j] * SCALE_C);
                sv[j] = e;
                l += e;
            }
            if (t > 0) { mbar_wait(smb + MB_PF, pfp); pfp ^= 1; }
            #pragma unroll
            for (int j = 0; j < 64; j += 2) {
                uint32_t sw = swz((uint32_t)(row*128 + j*2));
                __nv_bfloat16 h0 = __float2bfloat16(sv[j]), h1 = __float2bfloat16(sv[j+1]);
                __nv_bfloat16 l0 = __float2bfloat16(sv[j]   - __bfloat162float(h0));
                __nv_bfloat16 l1 = __float2bfloat16(sv[j+1] - __bfloat162float(h1));
                *(__nv_bfloat162*)(smraw + A2_P + sw)         = __halves2bfloat162(h0, h1);
                *(__nv_bfloat162*)(smraw + A2_P + 16384 + sw) = __halves2bfloat162(l0, l1);
            }
            fence_pa();
            if (elect_one()) mbar_arrive(smb + MB_PR);
            if (amI) {
                mbar_wait(smb + MB_PR, t & 1);
                const uint32_t Vst = smb + (s ? A2_V1 : A2_V0);
                bool first = true;
                #pragma unroll
                for (int p = 0; p < 3; p++) {
                    uint64_t pd = mk_desc(smb + A2_P + ((p == 2) ? 16384u : 0u));
                    uint64_t vd = mk_desc(Vst + ((p == 1) ? 16384u : 0u));
                    #pragma unroll
                    for (int k = 0; k < 4; k++) {
                        t5_mma_f16_ss(tmem + 128, pd + k*2, vd + k*2, IDESC_PV,
                                      (t == 0 && first) ? 0u : 1u);
                        first = false;
                    }
                }
                t5_commit(smb + MB_KVE + s*8);
                t5_commit(smb + MB_PF);
                if (t == nt - 1) t5_commit(smb + MB_OR);
                // issue QK(t+1) AFTER PV(t): overlaps softmax(t+1) without delaying PV
                if (t + 1 < nt) {
                    const int s2 = (t + 1) & 1;
                    mbar_wait(smb + MB_KVF + s2*8, ((t + 1) >> 1) & 1);
                    const uint32_t Kst2 = smb + (s2 ? A2_K1 : A2_K0);
                    bool f2 = true;
                    #pragma unroll
                    for (int p = 0; p < 3; p++) {
                        uint32_t ab = (p == 2) ? 352u : 256u;
                        uint32_t bo = (p == 1) ? 24576u : 0u;
                        #pragma unroll
                        for (int ks = 0; ks < 12; ks++) {
                            uint64_t kd = mk_desc(Kst2 + bo + (ks >> 2)*8192) + (ks & 3)*2;
                            t5_mma_f16_ts(tmem + s2*64, tmem + ab + ks*8, kd, IDESC_QK, f2 ? 0u : 1u);
                            f2 = false;
                        }
                    }
                    t5_commit(smb + MB_SD + s2*8);
                }
            }
        }
        sLi[row] = 1.f / l;
    }

    mbar_wait(smb + MB_OR, 0);
    t5_fence_after();
    __syncthreads();

    {
        const int row = ((warp & 3) << 5) | lane;
        const int dbase = (warp >> 2) * 64;
        float li = sLi[row];
        float ov[64];
        ldtm_x32((uint32_t*)ov, tmem + 128 + dbase);
        ldtm_x32((uint32_t*)(ov + 32), tmem + 128 + dbase + 32);
        t5_wait_ld(); t5_fence_before();
        const int R = b*SS + qt*128 + row;
        const int tile = R >> 7;
        #pragma unroll
        for (int j = 0; j < 64; j += 2) {
            int Ccol = h*128 + dbase + j;
            int chunk = Ccol >> 6, cin = Ccol & 63;
            uint32_t sw = swz((uint32_t)(row*128 + cin*2));
            size_t idx = ((size_t)(tile*32 + chunk) << 13) + (sw >> 1);
            float v0 = ov[j] * li, v1 = ov[j+1] * li;
            __nv_bfloat16 h0 = __float2bfloat16(v0), h1 = __float2bfloat16(v1);
            __nv_bfloat16 l0 = __float2bfloat16(v0 - __bfloat162float(h0));
            __nv_bfloat16 l1 = __float2bfloat16(v1 - __bfloat162float(h1));
            *(__nv_bfloat162*)&OHh[idx] = __halves2bfloat162(h0, h1);
            *(__nv_bfloat162*)&OHl[idx] = __halves2bfloat162(l0, l1);
        }
    }
    __syncthreads();
    if (tid == 0) {
        mbar_inval(smb + MB_KVF + 0); mbar_inval(smb + MB_KVF + 8);
        mbar_inval(smb + MB_KVE + 0); mbar_inval(smb + MB_KVE + 8);
        mbar_inval(smb + MB_SD + 0);  mbar_inval(smb + MB_SD + 8);
        mbar_inval(smb + MB_PR); mbar_inval(smb + MB_PF); mbar_inval(smb + MB_OR);
        mbar_inval(smb + MB_QL);
    }
    if (warp == 0) t5_dealloc(tmem, 512);
#endif
}

// ---------------- launch ----------------
extern "C" void kernel_launch(void* const* d_in, const int* in_sizes, int n_in,
                              void* d_out, int out_size)
{
    const float* x      = (const float*)d_in[0];
    const float* wq     = (const float*)d_in[1];
    const float* wkv_a  = (const float*)d_in[2];
    const float* kvw    = (const float*)d_in[3];
    const float* wkv_b  = (const float*)d_in[4];
    const float* wo     = (const float*)d_in[5];
    const float* cosp   = (const float*)d_in[6];
    const float* sinp   = (const float*)d_in[7];
    float* out = (float*)d_out;

    float *KV, *V;
    __nv_bfloat16 *Xh, *Xl, *WQh, *WQl, *WAh, *WAl, *WBkh, *WBkl, *WBvh, *WBvl, *WOh, *WOl;
    __nv_bfloat16 *CKVh, *CKVl, *OHh, *OHl, *Qp, *Kp, *Vp;
    cudaGetSymbolAddress((void**)&KV,   g_KV);
    cudaGetSymbolAddress((void**)&V,    g_V);
    cudaGetSymbolAddress((void**)&Xh,   g_Xh);   cudaGetSymbolAddress((void**)&Xl,   g_Xl);
    cudaGetSymbolAddress((void**)&WQh,  g_WQh);  cudaGetSymbolAddress((void**)&WQl,  g_WQl);
    cudaGetSymbolAddress((void**)&WAh,  g_WAh);  cudaGetSymbolAddress((void**)&WAl,  g_WAl);
    cudaGetSymbolAddress((void**)&WBkh, g_WBkh); cudaGetSymbolAddress((void**)&WBkl, g_WBkl);
    cudaGetSymbolAddress((void**)&WBvh, g_WBvh); cudaGetSymbolAddress((void**)&WBvl, g_WBvl);
    cudaGetSymbolAddress((void**)&WOh,  g_WOh);  cudaGetSymbolAddress((void**)&WOl,  g_WOl);
    cudaGetSymbolAddress((void**)&CKVh, g_CKVh); cudaGetSymbolAddress((void**)&CKVl, g_CKVl);
    cudaGetSymbolAddress((void**)&OHh,  g_OHh);  cudaGetSymbolAddress((void**)&OHl,  g_OHl);
    cudaGetSymbolAddress((void**)&Qp,   g_Qp);
    cudaGetSymbolAddress((void**)&Kp,   g_Kp);   cudaGetSymbolAddress((void**)&Vp,   g_Vp);

    cudaFuncSetAttribute(gemm_t5, cudaFuncAttributeMaxDynamicSharedMemorySize, GEMM_SMEM);
    cudaFuncSetAttribute(attn_t5, cudaFuncAttributeMaxDynamicSharedMemorySize, A2_SMEM);

    const int BIGGRP = 1 << 30;

    {
        size_t n;
        n = (size_t)BS*DIM;     split_A_kernel<<<(int)((n+255)/256), 256>>>(x, Xh, Xl, DIM, 32);
        n = (size_t)12*256*DIM; split_B_kernel<<<(int)((n+255)/256), 256>>>(wq, WQh, WQl, HH*QK, DIM, BIGGRP, 0, 0, n);
        n = (size_t)3*256*DIM;  split_B_kernel<<<(int)((n+255)/256), 256>>>(wkv_a, WAh, WAl, KVR+ROPE, DIM, BIGGRP, 0, 0, n);
        n = (size_t)8*256*KVR;  split_B_kernel<<<(int)((n+255)/256), 256>>>(wkv_b, WBkh, WBkl, HH*NOPE, KVR, 128, 256, 0, n);
        n = (size_t)8*256*KVR;  split_B_kernel<<<(int)((n+255)/256), 256>>>(wkv_b, WBvh, WBvl, HH*VDIM, KVR, 128, 256, 128, n);
        n = (size_t)8*256*DIM;  split_B_kernel<<<(int)((n+255)/256), 256>>>(wo, WOh, WOl, DIM, DIM, BIGGRP, 0, 0, n);
    }

    // 1. Q = X @ Wq^T -> Qp panels (fused rope)
    gemm_t5<<<dim3(12, 32), 128, GEMM_SMEM>>>(Xh, Xl, WQh, WQl, nullptr, Qp, HH*QK, 32, 1, cosp, sinp);
    // 2. KV = X @ Wkv_a^T (fp32)
    gemm_t5<<<dim3(3, 32), 128, GEMM_SMEM>>>(Xh, Xl, WAh, WAl, KV, nullptr, KVR+ROPE, 32, 0, nullptr, nullptr);
    // 3. rmsnorm -> CKV panels; rope(k_pe) -> Kp chunk 2
    kv_post_kernel<<<BS, 128>>>(KV, kvw, cosp, sinp, CKVh, CKVl, Kp);
    // 4. k_nope = CKV @ wb_k^T -> Kp chunks 0/1
    gemm_t5<<<dim3(8, 32), 128, GEMM_SMEM>>>(CKVh, CKVl, WBkh, WBkl, nullptr, Kp, HH*NOPE, 8, 2, nullptr, nullptr);
    // 5. v = CKV @ wb_v^T (fp32)
    gemm_t5<<<dim3(8, 32), 128, GEMM_SMEM>>>(CKVh, CKVl, WBvh, WBvl, V, nullptr, HH*VDIM, 8, 0, nullptr, nullptr);
    // 5b. V panels (transpose)
    vpanel_kernel<<<1024, 256>>>(V, Vp);
    // 6. tcgen05 flash attention -> OH panels
    attn_t5<<<dim3(16, HH, BB), 256, A2_SMEM>>>(Qp, Kp, Vp, OHh, OHl);
    // 7. out = OH @ wo^T (fp32)
    gemm_t5<<<dim3(8, 32), 128, GEMM_SMEM>>>(OHh, OHl, WOh, WOl, out, nullptr, DIM, 32, 0, nullptr, nullptr);
}